// round 1
// baseline (speedup 1.0000x reference)
#include <cuda_runtime.h>
#include <math.h>

#define MAXN 100000
#define MAXE 1600000
#define MAXB 256
#define H 64

// ---------------- scratch (static device globals; no allocation) ----------------
__device__ float  g_h[MAXN * H];        // node features
__device__ float  g_hW[MAXN * H];       // h @ conv_w[:64] + b
__device__ float4 g_stats[MAXN];        // (sum, sumsq, dot We0, dot We1) of hW row
__device__ int    g_deg[MAXN];          // incoming degree
__device__ int    g_off[MAXN + 1];      // CSR offsets
__device__ int    g_cur[MAXN];          // fill cursors
__device__ int    g_csr_src[MAXE];
__device__ float2 g_csr_ea[MAXE];
__device__ int    g_bsum[512];          // scan partials
__device__ float  g_lc[8];              // per-layer constants
__device__ float  g_pool[MAXB * H];
__device__ int    g_cnt[MAXB];

__device__ __forceinline__ float warp_sum(float v) {
    #pragma unroll
    for (int o = 16; o > 0; o >>= 1) v += __shfl_xor_sync(0xffffffffu, v, o);
    return v;
}
__device__ __forceinline__ float gelu_exact(float v) {
    return 0.5f * v * (1.0f + erff(v * 0.7071067811865476f));
}

// ---------------- zero init ----------------
__global__ void zero_kernel(int N, int B) {
    int i = blockIdx.x * blockDim.x + threadIdx.x;
    if (i < N) { g_deg[i] = 0; g_cur[i] = 0; }
    if (i < B * H) g_pool[i] = 0.0f;
    if (i < B) g_cnt[i] = 0;
}

// ---------------- node embedding MLP (warp per node) ----------------
__global__ __launch_bounds__(256) void node_embed_kernel(
    const float* __restrict__ x,
    const float* __restrict__ w1, const float* __restrict__ b1,
    const float* __restrict__ g1, const float* __restrict__ be1,
    const float* __restrict__ w2, const float* __restrict__ b2,
    const float* __restrict__ g2, const float* __restrict__ be2, int N)
{
    __shared__ float ws[H * H];
    int t = threadIdx.x;
    for (int i = t; i < H * H; i += 256) ws[i] = w2[i];
    __syncthreads();
    int node = blockIdx.x * 8 + (t >> 5);
    int lane = t & 31;
    if (node >= N) return;
    int c0 = 2 * lane, c1 = c0 + 1;
    float x0 = x[node * 2], x1 = x[node * 2 + 1];
    float p0 = fmaf(x1, w1[H + c0], fmaf(x0, w1[c0], b1[c0]));
    float p1 = fmaf(x1, w1[H + c1], fmaf(x0, w1[c1], b1[c1]));
    float s = warp_sum(p0 + p1);
    float q = warp_sum(p0 * p0 + p1 * p1);
    float mu = s * (1.0f / H);
    float r  = rsqrtf(q * (1.0f / H) - mu * mu + 1e-5f);
    float a0 = gelu_exact((p0 - mu) * r * g1[c0] + be1[c0]);
    float a1 = gelu_exact((p1 - mu) * r * g1[c1] + be1[c1]);
    float acc0 = b2[c0], acc1 = b2[c1];
    #pragma unroll
    for (int k = 0; k < 32; k++) {
        float u = __shfl_sync(0xffffffffu, a0, k);
        float v = __shfl_sync(0xffffffffu, a1, k);
        const float* r0 = &ws[(2 * k) * H];
        const float* r1 = &ws[(2 * k + 1) * H];
        acc0 = fmaf(u, r0[c0], acc0); acc0 = fmaf(v, r1[c0], acc0);
        acc1 = fmaf(u, r0[c1], acc1); acc1 = fmaf(v, r1[c1], acc1);
    }
    s = warp_sum(acc0 + acc1);
    q = warp_sum(acc0 * acc0 + acc1 * acc1);
    mu = s * (1.0f / H);
    r  = rsqrtf(q * (1.0f / H) - mu * mu + 1e-5f);
    g_h[node * H + c0] = gelu_exact((acc0 - mu) * r * g2[c0] + be2[c0]);
    g_h[node * H + c1] = gelu_exact((acc1 - mu) * r * g2[c1] + be2[c1]);
}

// ---------------- CSR build ----------------
__global__ void count_deg_kernel(const int* __restrict__ ei, int E) {
    int e = blockIdx.x * blockDim.x + threadIdx.x;
    if (e < E) atomicAdd(&g_deg[ei[E + e]], 1);
}

__global__ void scan_local_kernel(int N) {
    __shared__ int wsums[16];
    int t = threadIdx.x, lane = t & 31, w = t >> 5;
    int i = blockIdx.x * 512 + t;
    int x = (i < N) ? g_deg[i] : 0;
    int v = x;
    #pragma unroll
    for (int o = 1; o < 32; o <<= 1) { int n = __shfl_up_sync(0xffffffffu, v, o); if (lane >= o) v += n; }
    if (lane == 31) wsums[w] = v;
    __syncthreads();
    if (w == 0) {
        int s = (lane < 16) ? wsums[lane] : 0;
        #pragma unroll
        for (int o = 1; o < 16; o <<= 1) { int n = __shfl_up_sync(0xffffffffu, s, o); if (lane >= o) s += n; }
        if (lane < 16) wsums[lane] = s;
    }
    __syncthreads();
    int off = (w > 0) ? wsums[w - 1] : 0;
    int incl = v + off;
    if (i < N) g_off[i] = incl - x;
    if (t == 511) g_bsum[blockIdx.x] = incl;
}

__global__ void scan_bsum_kernel(int nblk) {
    __shared__ int wsums[8];
    int t = threadIdx.x, lane = t & 31, w = t >> 5;
    int x = (t < nblk) ? g_bsum[t] : 0;
    int v = x;
    #pragma unroll
    for (int o = 1; o < 32; o <<= 1) { int n = __shfl_up_sync(0xffffffffu, v, o); if (lane >= o) v += n; }
    if (lane == 31) wsums[w] = v;
    __syncthreads();
    if (w == 0) {
        int s = (lane < 8) ? wsums[lane] : 0;
        #pragma unroll
        for (int o = 1; o < 8; o <<= 1) { int n = __shfl_up_sync(0xffffffffu, s, o); if (lane >= o && lane < 8) s += n; }
        if (lane < 8) wsums[lane] = s;
    }
    __syncthreads();
    int off = (w > 0) ? wsums[w - 1] : 0;
    if (t < nblk) g_bsum[t] = v + off - x;   // exclusive
}

__global__ void scan_add_kernel(int N, int E) {
    int i = blockIdx.x * 512 + threadIdx.x;
    if (i < N) g_off[i] += g_bsum[blockIdx.x];
    if (i == 0) g_off[N] = E;
}

__global__ void fill_csr_kernel(const int* __restrict__ ei, const float* __restrict__ ea, int E) {
    int e = blockIdx.x * blockDim.x + threadIdx.x;
    if (e >= E) return;
    int d = ei[E + e];
    int p = g_off[d] + atomicAdd(&g_cur[d], 1);
    g_csr_src[p] = ei[e];
    g_csr_ea[p] = *(const float2*)&ea[2 * e];
}

// ---------------- per-layer: constants ----------------
__global__ void prep_layer_kernel(const float* __restrict__ cw) {
    int lane = threadIdx.x;
    float a0 = cw[64 * H + 2 * lane], a1 = cw[64 * H + 2 * lane + 1];
    float b0 = cw[65 * H + 2 * lane], b1 = cw[65 * H + 2 * lane + 1];
    float SW0 = warp_sum(a0 + a1);
    float SW1 = warp_sum(b0 + b1);
    float Q0  = warp_sum(a0 * a0 + a1 * a1);
    float Q1  = warp_sum(b0 * b0 + b1 * b1);
    float D01 = warp_sum(a0 * b0 + a1 * b1);
    if (lane == 0) { g_lc[0] = SW0; g_lc[1] = SW1; g_lc[2] = Q0; g_lc[3] = Q1; g_lc[4] = D01; }
}

// ---------------- per-layer: hW = h@W + b, plus LN stats ----------------
__global__ __launch_bounds__(256) void hw_stats_kernel(
    const float* __restrict__ cw, const float* __restrict__ cb, int N)
{
    __shared__ float ws[H * H];
    __shared__ float we[2 * H];
    int t = threadIdx.x;
    for (int i = t; i < H * H; i += 256) ws[i] = cw[i];
    if (t < 2 * H) we[t] = cw[64 * H + t];
    __syncthreads();
    int node = blockIdx.x * 8 + (t >> 5);
    int lane = t & 31;
    if (node >= N) return;
    int c0 = 2 * lane, c1 = c0 + 1;
    float2 hv = *(const float2*)&g_h[node * H + c0];
    float h0 = hv.x, h1 = hv.y;
    float acc0 = cb[c0], acc1 = cb[c1];
    #pragma unroll
    for (int k = 0; k < 32; k++) {
        float u = __shfl_sync(0xffffffffu, h0, k);
        float v = __shfl_sync(0xffffffffu, h1, k);
        const float* r0 = &ws[(2 * k) * H];
        const float* r1 = &ws[(2 * k + 1) * H];
        acc0 = fmaf(u, r0[c0], acc0); acc0 = fmaf(v, r1[c0], acc0);
        acc1 = fmaf(u, r0[c1], acc1); acc1 = fmaf(v, r1[c1], acc1);
    }
    *(float2*)&g_hW[node * H + c0] = make_float2(acc0, acc1);
    float w00 = we[c0], w01 = we[c1];
    float w10 = we[H + c0], w11 = we[H + c1];
    float S1 = warp_sum(acc0 + acc1);
    float S2 = warp_sum(acc0 * acc0 + acc1 * acc1);
    float D0 = warp_sum(acc0 * w00 + acc1 * w01);
    float D1 = warp_sum(acc0 * w10 + acc1 * w11);
    if (lane == 0) g_stats[node] = make_float4(S1, S2, D0, D1);
}

// ---------------- per-layer: aggregate + residual/LN update (warp per dst) ----------------
__global__ __launch_bounds__(256) void conv_agg_kernel(
    const float* __restrict__ cw,
    const float* __restrict__ mg, const float* __restrict__ mb,
    const float* __restrict__ ng, const float* __restrict__ nb,
    const float* __restrict__ og, const float* __restrict__ ob, int N)
{
    int t = threadIdx.x;
    int node = blockIdx.x * 8 + (t >> 5);
    int lane = t & 31;
    if (node >= N) return;
    int c0 = 2 * lane, c1 = c0 + 1;
    float We00 = cw[64 * H + c0], We01 = cw[64 * H + c1];
    float We10 = cw[65 * H + c0], We11 = cw[65 * H + c1];
    float mg0 = mg[c0], mg1 = mg[c1], mb0 = mb[c0], mb1 = mb[c1];
    float SW0 = g_lc[0], SW1 = g_lc[1], Q0 = g_lc[2], Q1 = g_lc[3], D01 = g_lc[4];
    int beg = g_off[node], end = g_off[node + 1];
    float acc0 = 0.0f, acc1 = 0.0f;
    for (int i = beg; i < end; i++) {
        int s = g_csr_src[i];
        float2 ea = g_csr_ea[i];
        float4 st = g_stats[s];
        float2 hv = *(const float2*)&g_hW[s * H + c0];
        float sum = st.x + ea.x * SW0 + ea.y * SW1;
        float ssq = st.y + ea.x * ea.x * Q0 + ea.y * ea.y * Q1
                  + 2.0f * (ea.x * st.z + ea.y * st.w + ea.x * ea.y * D01);
        float mu  = sum * (1.0f / H);
        float var = ssq * (1.0f / H) - mu * mu;
        float r   = rsqrtf(var + 1e-5f);
        float v0 = hv.x + ea.x * We00 + ea.y * We10;
        float v1 = hv.y + ea.x * We01 + ea.y * We11;
        acc0 += gelu_exact((v0 - mu) * r * mg0 + mb0);
        acc1 += gelu_exact((v1 - mu) * r * mg1 + mb1);
    }
    float inv = 1.0f / fmaxf((float)(end - beg), 1.0f);
    float2 hrow = *(const float2*)&g_h[node * H + c0];
    float t0 = acc0 * inv + hrow.x;
    float t1 = acc1 * inv + hrow.y;
    float s1 = warp_sum(t0 + t1);
    float s2 = warp_sum(t0 * t0 + t1 * t1);
    float mu = s1 * (1.0f / H);
    float r  = rsqrtf(s2 * (1.0f / H) - mu * mu + 1e-5f);
    float co0 = (t0 - mu) * r * ng[c0] + nb[c0];
    float co1 = (t1 - mu) * r * ng[c1] + nb[c1];
    s1 = warp_sum(co0 + co1);
    s2 = warp_sum(co0 * co0 + co1 * co1);
    mu = s1 * (1.0f / H);
    r  = rsqrtf(s2 * (1.0f / H) - mu * mu + 1e-5f);
    float u0 = (co0 - mu) * r * og[c0] + ob[c0];
    float u1 = (co1 - mu) * r * og[c1] + ob[c1];
    *(float2*)&g_h[node * H + c0] = make_float2(hrow.x + u0, hrow.y + u1);
}

// ---------------- global mean pool ----------------
__global__ __launch_bounds__(256) void pool_kernel(const int* __restrict__ batch, int N) {
    int t = threadIdx.x;
    int node = blockIdx.x * 8 + (t >> 5);
    int lane = t & 31;
    if (node >= N) return;
    int b = batch[node];
    float2 hv = *(const float2*)&g_h[node * H + 2 * lane];
    atomicAdd(&g_pool[b * H + 2 * lane], hv.x);
    atomicAdd(&g_pool[b * H + 2 * lane + 1], hv.y);
    if (lane == 0) atomicAdd(&g_cnt[b], 1);
}

// ---------------- head MLP (warp per graph) ----------------
__global__ __launch_bounds__(256) void head_kernel(
    const float* __restrict__ w1, const float* __restrict__ b1,
    const float* __restrict__ gg1, const float* __restrict__ bb1,
    const float* __restrict__ w2, const float* __restrict__ b2,
    const float* __restrict__ gg2, const float* __restrict__ bb2,
    const float* __restrict__ w3, const float* __restrict__ b3,
    float* __restrict__ out, int B)
{
    int t = threadIdx.x;
    int g = blockIdx.x * 8 + (t >> 5);
    int lane = t & 31;
    if (g >= B) return;
    float inv = 1.0f / fmaxf((float)g_cnt[g], 1.0f);
    int c0 = 2 * lane, c1 = c0 + 1;
    float v0 = g_pool[g * H + c0] * inv;
    float v1 = g_pool[g * H + c1] * inv;
    float acc0 = b1[c0], acc1 = b1[c1];
    #pragma unroll
    for (int k = 0; k < 32; k++) {
        float a = __shfl_sync(0xffffffffu, v0, k);
        float b_ = __shfl_sync(0xffffffffu, v1, k);
        acc0 = fmaf(a, w1[(2 * k) * H + c0], acc0); acc0 = fmaf(b_, w1[(2 * k + 1) * H + c0], acc0);
        acc1 = fmaf(a, w1[(2 * k) * H + c1], acc1); acc1 = fmaf(b_, w1[(2 * k + 1) * H + c1], acc1);
    }
    float s1 = warp_sum(acc0 + acc1);
    float s2 = warp_sum(acc0 * acc0 + acc1 * acc1);
    float mu = s1 * (1.0f / H);
    float r  = rsqrtf(s2 * (1.0f / H) - mu * mu + 1e-5f);
    float a0 = fmaxf((acc0 - mu) * r * gg1[c0] + bb1[c0], 0.0f);
    float a1 = fmaxf((acc1 - mu) * r * gg1[c1] + bb1[c1], 0.0f);
    float acc = b2[lane];
    #pragma unroll
    for (int k = 0; k < 32; k++) {
        float a = __shfl_sync(0xffffffffu, a0, k);
        float bb = __shfl_sync(0xffffffffu, a1, k);
        acc = fmaf(a, w2[(2 * k) * 32 + lane], acc);
        acc = fmaf(bb, w2[(2 * k + 1) * 32 + lane], acc);
    }
    s1 = warp_sum(acc);
    s2 = warp_sum(acc * acc);
    mu = s1 * (1.0f / 32.0f);
    r  = rsqrtf(s2 * (1.0f / 32.0f) - mu * mu + 1e-5f);
    float z = fmaxf((acc - mu) * r * gg2[lane] + bb2[lane], 0.0f);
    float o = warp_sum(z * w3[lane]);
    if (lane == 0) out[g] = o + b3[0];
}

// ---------------- launch ----------------
extern "C" void kernel_launch(void* const* d_in, const int* in_sizes, int n_in,
                              void* d_out, int out_size)
{
    const float* x        = (const float*)d_in[0];
    const float* edge_attr= (const float*)d_in[1];
    const float* ne_w1 = (const float*)d_in[2];
    const float* ne_b1 = (const float*)d_in[3];
    const float* ne_g1 = (const float*)d_in[4];
    const float* ne_be1= (const float*)d_in[5];
    const float* ne_w2 = (const float*)d_in[6];
    const float* ne_b2 = (const float*)d_in[7];
    const float* ne_g2 = (const float*)d_in[8];
    const float* ne_be2= (const float*)d_in[9];
    const float* conv_w = (const float*)d_in[10];
    const float* conv_b = (const float*)d_in[11];
    const float* conv_mg= (const float*)d_in[12];
    const float* conv_mb= (const float*)d_in[13];
    const float* conv_ng= (const float*)d_in[14];
    const float* conv_nb= (const float*)d_in[15];
    const float* out_ng = (const float*)d_in[16];
    const float* out_nb = (const float*)d_in[17];
    const float* m_w1 = (const float*)d_in[18];
    const float* m_b1 = (const float*)d_in[19];
    const float* m_g1 = (const float*)d_in[20];
    const float* m_be1= (const float*)d_in[21];
    const float* m_w2 = (const float*)d_in[22];
    const float* m_b2 = (const float*)d_in[23];
    const float* m_g2 = (const float*)d_in[24];
    const float* m_be2= (const float*)d_in[25];
    const float* m_w3 = (const float*)d_in[26];
    const float* m_b3 = (const float*)d_in[27];
    const int* edge_index = (const int*)d_in[28];
    const int* batch      = (const int*)d_in[29];

    int N = in_sizes[0] / 2;
    int E = in_sizes[1] / 2;
    int B = out_size;

    int NB8 = (N + 7) / 8;
    int EB  = (E + 255) / 256;
    int nscan = (N + 511) / 512;

    zero_kernel<<<(N + 255) / 256, 256>>>(N, B);
    node_embed_kernel<<<NB8, 256>>>(x, ne_w1, ne_b1, ne_g1, ne_be1,
                                    ne_w2, ne_b2, ne_g2, ne_be2, N);
    count_deg_kernel<<<EB, 256>>>(edge_index, E);
    scan_local_kernel<<<nscan, 512>>>(N);
    scan_bsum_kernel<<<1, 256>>>(nscan);
    scan_add_kernel<<<nscan, 512>>>(N, E);
    fill_csr_kernel<<<EB, 256>>>(edge_index, edge_attr, E);

    for (int l = 0; l < 3; l++) {
        const float* cw = conv_w + l * (H + 2) * H;
        prep_layer_kernel<<<1, 32>>>(cw);
        hw_stats_kernel<<<NB8, 256>>>(cw, conv_b + l * H, N);
        conv_agg_kernel<<<NB8, 256>>>(cw,
            conv_mg + l * H, conv_mb + l * H,
            conv_ng + l * H, conv_nb + l * H,
            out_ng + l * H, out_nb + l * H, N);
    }

    pool_kernel<<<NB8, 256>>>(batch, N);
    head_kernel<<<(B + 7) / 8, 256>>>(m_w1, m_b1, m_g1, m_be1,
                                      m_w2, m_b2, m_g2, m_be2,
                                      m_w3, m_b3, (float*)d_out, B);
}

// round 2
// speedup vs baseline: 2.1013x; 2.1013x over previous
#include <cuda_runtime.h>
#include <math.h>

#define MAXN 100000
#define MAXE 1600000
#define MAXB 256
#define H 64

// ---------------- scratch (static device globals; no allocation) ----------------
__device__ float  g_h[MAXN * H];        // node features
__device__ float  g_hW[MAXN * H];       // h @ conv_w[:64] + b
__device__ float4 g_stats[MAXN];        // (sum, sumsq, dot We0, dot We1) of hW row
__device__ int    g_deg[MAXN];          // incoming degree
__device__ int    g_off[MAXN + 1];      // CSR offsets
__device__ int    g_cur[MAXN];          // fill cursors
__device__ int    g_csr_src[MAXE];
__device__ float2 g_csr_ea[MAXE];
__device__ int    g_bsum[512];          // scan partials
__device__ float  g_lc[8];              // per-layer constants
__device__ float  g_pool[MAXB * H];
__device__ int    g_cnt[MAXB];

__device__ __forceinline__ float warp_sum(float v) {
    #pragma unroll
    for (int o = 16; o > 0; o >>= 1) v += __shfl_xor_sync(0xffffffffu, v, o);
    return v;
}
__device__ __forceinline__ float gelu_exact(float v) {
    return 0.5f * v * (1.0f + erff(v * 0.7071067811865476f));
}
// fast gelu via HW tanh (MUFU.TANH); |err| vs exact erf-gelu ~3e-4 abs
__device__ __forceinline__ float gelu_fast(float x) {
    float x2 = x * x;
    float x3 = x2 * x;
    float u = fmaf(0.0356774081f, x3, 0.7978845608f * x);
    float t;
    asm("tanh.approx.f32 %0, %1;" : "=f"(t) : "f"(u));
    float hx = 0.5f * x;
    return fmaf(hx, t, hx);
}

// ---------------- zero init ----------------
__global__ void zero_kernel(int N, int B) {
    int i = blockIdx.x * blockDim.x + threadIdx.x;
    if (i < N) { g_deg[i] = 0; g_cur[i] = 0; }
    if (i < B * H) g_pool[i] = 0.0f;
    if (i < B) g_cnt[i] = 0;
}

// ---------------- node embedding MLP (warp per node) ----------------
__global__ __launch_bounds__(256) void node_embed_kernel(
    const float* __restrict__ x,
    const float* __restrict__ w1, const float* __restrict__ b1,
    const float* __restrict__ g1, const float* __restrict__ be1,
    const float* __restrict__ w2, const float* __restrict__ b2,
    const float* __restrict__ g2, const float* __restrict__ be2, int N)
{
    __shared__ float ws[H * H];
    int t = threadIdx.x;
    for (int i = t; i < H * H; i += 256) ws[i] = w2[i];
    __syncthreads();
    int node = blockIdx.x * 8 + (t >> 5);
    int lane = t & 31;
    if (node >= N) return;
    int c0 = 2 * lane, c1 = c0 + 1;
    float x0 = x[node * 2], x1 = x[node * 2 + 1];
    float p0 = fmaf(x1, w1[H + c0], fmaf(x0, w1[c0], b1[c0]));
    float p1 = fmaf(x1, w1[H + c1], fmaf(x0, w1[c1], b1[c1]));
    float s = warp_sum(p0 + p1);
    float q = warp_sum(p0 * p0 + p1 * p1);
    float mu = s * (1.0f / H);
    float r  = rsqrtf(q * (1.0f / H) - mu * mu + 1e-5f);
    float a0 = gelu_exact((p0 - mu) * r * g1[c0] + be1[c0]);
    float a1 = gelu_exact((p1 - mu) * r * g1[c1] + be1[c1]);
    float acc0 = b2[c0], acc1 = b2[c1];
    #pragma unroll
    for (int k = 0; k < 32; k++) {
        float u = __shfl_sync(0xffffffffu, a0, k);
        float v = __shfl_sync(0xffffffffu, a1, k);
        const float* r0 = &ws[(2 * k) * H];
        const float* r1 = &ws[(2 * k + 1) * H];
        acc0 = fmaf(u, r0[c0], acc0); acc0 = fmaf(v, r1[c0], acc0);
        acc1 = fmaf(u, r0[c1], acc1); acc1 = fmaf(v, r1[c1], acc1);
    }
    s = warp_sum(acc0 + acc1);
    q = warp_sum(acc0 * acc0 + acc1 * acc1);
    mu = s * (1.0f / H);
    r  = rsqrtf(q * (1.0f / H) - mu * mu + 1e-5f);
    g_h[node * H + c0] = gelu_exact((acc0 - mu) * r * g2[c0] + be2[c0]);
    g_h[node * H + c1] = gelu_exact((acc1 - mu) * r * g2[c1] + be2[c1]);
}

// ---------------- CSR build ----------------
__global__ void count_deg_kernel(const int* __restrict__ ei, int E) {
    int e = blockIdx.x * blockDim.x + threadIdx.x;
    if (e < E) atomicAdd(&g_deg[ei[E + e]], 1);
}

__global__ void scan_local_kernel(int N) {
    __shared__ int wsums[16];
    int t = threadIdx.x, lane = t & 31, w = t >> 5;
    int i = blockIdx.x * 512 + t;
    int x = (i < N) ? g_deg[i] : 0;
    int v = x;
    #pragma unroll
    for (int o = 1; o < 32; o <<= 1) { int n = __shfl_up_sync(0xffffffffu, v, o); if (lane >= o) v += n; }
    if (lane == 31) wsums[w] = v;
    __syncthreads();
    if (w == 0) {
        int s = (lane < 16) ? wsums[lane] : 0;
        #pragma unroll
        for (int o = 1; o < 16; o <<= 1) { int n = __shfl_up_sync(0xffffffffu, s, o); if (lane >= o) s += n; }
        if (lane < 16) wsums[lane] = s;
    }
    __syncthreads();
    int off = (w > 0) ? wsums[w - 1] : 0;
    int incl = v + off;
    if (i < N) g_off[i] = incl - x;
    if (t == 511) g_bsum[blockIdx.x] = incl;
}

__global__ void scan_bsum_kernel(int nblk) {
    __shared__ int wsums[8];
    int t = threadIdx.x, lane = t & 31, w = t >> 5;
    int x = (t < nblk) ? g_bsum[t] : 0;
    int v = x;
    #pragma unroll
    for (int o = 1; o < 32; o <<= 1) { int n = __shfl_up_sync(0xffffffffu, v, o); if (lane >= o) v += n; }
    if (lane == 31) wsums[w] = v;
    __syncthreads();
    if (w == 0) {
        int s = (lane < 8) ? wsums[lane] : 0;
        #pragma unroll
        for (int o = 1; o < 8; o <<= 1) { int n = __shfl_up_sync(0xffffffffu, s, o); if (lane >= o && lane < 8) s += n; }
        if (lane < 8) wsums[lane] = s;
    }
    __syncthreads();
    int off = (w > 0) ? wsums[w - 1] : 0;
    if (t < nblk) g_bsum[t] = v + off - x;   // exclusive
}

__global__ void scan_add_kernel(int N, int E) {
    int i = blockIdx.x * 512 + threadIdx.x;
    if (i < N) g_off[i] += g_bsum[blockIdx.x];
    if (i == 0) g_off[N] = E;
}

__global__ void fill_csr_kernel(const int* __restrict__ ei, const float* __restrict__ ea, int E) {
    int e = blockIdx.x * blockDim.x + threadIdx.x;
    if (e >= E) return;
    int d = ei[E + e];
    int p = g_off[d] + atomicAdd(&g_cur[d], 1);
    g_csr_src[p] = ei[e];
    g_csr_ea[p] = *(const float2*)&ea[2 * e];
}

// ---------------- per-layer: constants ----------------
__global__ void prep_layer_kernel(const float* __restrict__ cw) {
    int lane = threadIdx.x;
    float a0 = cw[64 * H + 2 * lane], a1 = cw[64 * H + 2 * lane + 1];
    float b0 = cw[65 * H + 2 * lane], b1 = cw[65 * H + 2 * lane + 1];
    float SW0 = warp_sum(a0 + a1);
    float SW1 = warp_sum(b0 + b1);
    float Q0  = warp_sum(a0 * a0 + a1 * a1);
    float Q1  = warp_sum(b0 * b0 + b1 * b1);
    float D01 = warp_sum(a0 * b0 + a1 * b1);
    if (lane == 0) { g_lc[0] = SW0; g_lc[1] = SW1; g_lc[2] = Q0; g_lc[3] = Q1; g_lc[4] = D01; }
}

// ---------------- per-layer: hW = h@W + b, plus LN stats ----------------
__global__ __launch_bounds__(256) void hw_stats_kernel(
    const float* __restrict__ cw, const float* __restrict__ cb, int N)
{
    __shared__ float ws[H * H];
    __shared__ float we[2 * H];
    int t = threadIdx.x;
    for (int i = t; i < H * H; i += 256) ws[i] = cw[i];
    if (t < 2 * H) we[t] = cw[64 * H + t];
    __syncthreads();
    int node = blockIdx.x * 8 + (t >> 5);
    int lane = t & 31;
    if (node >= N) return;
    int c0 = 2 * lane, c1 = c0 + 1;
    float2 hv = *(const float2*)&g_h[node * H + c0];
    float h0 = hv.x, h1 = hv.y;
    float acc0 = cb[c0], acc1 = cb[c1];
    #pragma unroll
    for (int k = 0; k < 32; k++) {
        float u = __shfl_sync(0xffffffffu, h0, k);
        float v = __shfl_sync(0xffffffffu, h1, k);
        const float* r0 = &ws[(2 * k) * H];
        const float* r1 = &ws[(2 * k + 1) * H];
        acc0 = fmaf(u, r0[c0], acc0); acc0 = fmaf(v, r1[c0], acc0);
        acc1 = fmaf(u, r0[c1], acc1); acc1 = fmaf(v, r1[c1], acc1);
    }
    *(float2*)&g_hW[node * H + c0] = make_float2(acc0, acc1);
    float w00 = we[c0], w01 = we[c1];
    float w10 = we[H + c0], w11 = we[H + c1];
    float S1 = warp_sum(acc0 + acc1);
    float S2 = warp_sum(acc0 * acc0 + acc1 * acc1);
    float D0 = warp_sum(acc0 * w00 + acc1 * w01);
    float D1 = warp_sum(acc0 * w10 + acc1 * w11);
    if (lane == 0) g_stats[node] = make_float4(S1, S2, D0, D1);
}

// ---------------- per-layer: aggregate + residual/LN update (warp per dst) ----------------
// Lane-parallel edge metadata: lane i computes edge (base+i)'s LN scalars, then
// the warp sweeps edges broadcasting (src, ea, mu, r) via shfl while gathering
// the coalesced hW row. do_pool!=0 fuses the global mean pool (last layer).
__global__ __launch_bounds__(256) void conv_agg_kernel(
    const float* __restrict__ cw,
    const float* __restrict__ mg, const float* __restrict__ mb,
    const float* __restrict__ ng, const float* __restrict__ nb,
    const float* __restrict__ og, const float* __restrict__ ob,
    const int* __restrict__ batch, int do_pool, int N)
{
    int t = threadIdx.x;
    int node = blockIdx.x * 8 + (t >> 5);
    int lane = t & 31;
    if (node >= N) return;
    int c0 = 2 * lane, c1 = c0 + 1;
    float We00 = cw[64 * H + c0], We01 = cw[64 * H + c1];
    float We10 = cw[65 * H + c0], We11 = cw[65 * H + c1];
    float mg0 = mg[c0], mg1 = mg[c1], mb0 = mb[c0], mb1 = mb[c1];
    float SW0 = g_lc[0], SW1 = g_lc[1], Q0 = g_lc[2], Q1 = g_lc[3], D01 = g_lc[4];
    int beg = g_off[node], end = g_off[node + 1];
    float acc0 = 0.0f, acc1 = 0.0f;
    for (int base = beg; base < end; base += 32) {
        int cnt = min(32, end - base);
        int   s_l = 0;
        float eax_l = 0.0f, eay_l = 0.0f, mu_l = 0.0f, r_l = 0.0f;
        if (lane < cnt) {
            s_l = g_csr_src[base + lane];
            float2 ea = g_csr_ea[base + lane];
            float4 st = g_stats[s_l];
            float sum = st.x + ea.x * SW0 + ea.y * SW1;
            float ssq = st.y + ea.x * ea.x * Q0 + ea.y * ea.y * Q1
                      + 2.0f * (ea.x * st.z + ea.y * st.w + ea.x * ea.y * D01);
            mu_l = sum * (1.0f / H);
            float var = ssq * (1.0f / H) - mu_l * mu_l;
            r_l = rsqrtf(var + 1e-5f);
            eax_l = ea.x; eay_l = ea.y;
        }
        #pragma unroll 4
        for (int j = 0; j < cnt; j++) {
            int   ss = __shfl_sync(0xffffffffu, s_l, j);
            float ex = __shfl_sync(0xffffffffu, eax_l, j);
            float ey = __shfl_sync(0xffffffffu, eay_l, j);
            float m  = __shfl_sync(0xffffffffu, mu_l, j);
            float rj = __shfl_sync(0xffffffffu, r_l, j);
            float2 hv = *(const float2*)&g_hW[ss * H + c0];
            // arg = (hW + ex*WeA + ey*WeB - m) * rj * mg + mb  = hW*A + K
            float A0 = rj * mg0, A1 = rj * mg1;
            float e0 = fmaf(ey, We10, ex * We00) - m;
            float e1 = fmaf(ey, We11, ex * We01) - m;
            float K0 = fmaf(e0, A0, mb0);
            float K1 = fmaf(e1, A1, mb1);
            acc0 += gelu_fast(fmaf(hv.x, A0, K0));
            acc1 += gelu_fast(fmaf(hv.y, A1, K1));
        }
    }
    float inv = 1.0f / fmaxf((float)(end - beg), 1.0f);
    float2 hrow = *(const float2*)&g_h[node * H + c0];
    float t0 = acc0 * inv + hrow.x;
    float t1 = acc1 * inv + hrow.y;
    float s1 = warp_sum(t0 + t1);
    float s2 = warp_sum(t0 * t0 + t1 * t1);
    float mu = s1 * (1.0f / H);
    float r  = rsqrtf(s2 * (1.0f / H) - mu * mu + 1e-5f);
    float co0 = (t0 - mu) * r * ng[c0] + nb[c0];
    float co1 = (t1 - mu) * r * ng[c1] + nb[c1];
    s1 = warp_sum(co0 + co1);
    s2 = warp_sum(co0 * co0 + co1 * co1);
    mu = s1 * (1.0f / H);
    r  = rsqrtf(s2 * (1.0f / H) - mu * mu + 1e-5f);
    float u0 = (co0 - mu) * r * og[c0] + ob[c0];
    float u1 = (co1 - mu) * r * og[c1] + ob[c1];
    float nh0 = hrow.x + u0, nh1 = hrow.y + u1;
    if (!do_pool) {
        *(float2*)&g_h[node * H + c0] = make_float2(nh0, nh1);
    } else {
        int b = batch[node];
        atomicAdd(&g_pool[b * H + c0], nh0);
        atomicAdd(&g_pool[b * H + c1], nh1);
        if (lane == 0) atomicAdd(&g_cnt[b], 1);
    }
}

// ---------------- head MLP (warp per graph) ----------------
__global__ __launch_bounds__(256) void head_kernel(
    const float* __restrict__ w1, const float* __restrict__ b1,
    const float* __restrict__ gg1, const float* __restrict__ bb1,
    const float* __restrict__ w2, const float* __restrict__ b2,
    const float* __restrict__ gg2, const float* __restrict__ bb2,
    const float* __restrict__ w3, const float* __restrict__ b3,
    float* __restrict__ out, int B)
{
    int t = threadIdx.x;
    int g = blockIdx.x * 8 + (t >> 5);
    int lane = t & 31;
    if (g >= B) return;
    float inv = 1.0f / fmaxf((float)g_cnt[g], 1.0f);
    int c0 = 2 * lane, c1 = c0 + 1;
    float v0 = g_pool[g * H + c0] * inv;
    float v1 = g_pool[g * H + c1] * inv;
    float acc0 = b1[c0], acc1 = b1[c1];
    #pragma unroll
    for (int k = 0; k < 32; k++) {
        float a = __shfl_sync(0xffffffffu, v0, k);
        float b_ = __shfl_sync(0xffffffffu, v1, k);
        acc0 = fmaf(a, w1[(2 * k) * H + c0], acc0); acc0 = fmaf(b_, w1[(2 * k + 1) * H + c0], acc0);
        acc1 = fmaf(a, w1[(2 * k) * H + c1], acc1); acc1 = fmaf(b_, w1[(2 * k + 1) * H + c1], acc1);
    }
    float s1 = warp_sum(acc0 + acc1);
    float s2 = warp_sum(acc0 * acc0 + acc1 * acc1);
    float mu = s1 * (1.0f / H);
    float r  = rsqrtf(s2 * (1.0f / H) - mu * mu + 1e-5f);
    float a0 = fmaxf((acc0 - mu) * r * gg1[c0] + bb1[c0], 0.0f);
    float a1 = fmaxf((acc1 - mu) * r * gg1[c1] + bb1[c1], 0.0f);
    float acc = b2[lane];
    #pragma unroll
    for (int k = 0; k < 32; k++) {
        float a = __shfl_sync(0xffffffffu, a0, k);
        float bb = __shfl_sync(0xffffffffu, a1, k);
        acc = fmaf(a, w2[(2 * k) * 32 + lane], acc);
        acc = fmaf(bb, w2[(2 * k + 1) * 32 + lane], acc);
    }
    s1 = warp_sum(acc);
    s2 = warp_sum(acc * acc);
    mu = s1 * (1.0f / 32.0f);
    r  = rsqrtf(s2 * (1.0f / 32.0f) - mu * mu + 1e-5f);
    float z = fmaxf((acc - mu) * r * gg2[lane] + bb2[lane], 0.0f);
    float o = warp_sum(z * w3[lane]);
    if (lane == 0) out[g] = o + b3[0];
}

// ---------------- launch ----------------
extern "C" void kernel_launch(void* const* d_in, const int* in_sizes, int n_in,
                              void* d_out, int out_size)
{
    const float* x        = (const float*)d_in[0];
    const float* edge_attr= (const float*)d_in[1];
    const float* ne_w1 = (const float*)d_in[2];
    const float* ne_b1 = (const float*)d_in[3];
    const float* ne_g1 = (const float*)d_in[4];
    const float* ne_be1= (const float*)d_in[5];
    const float* ne_w2 = (const float*)d_in[6];
    const float* ne_b2 = (const float*)d_in[7];
    const float* ne_g2 = (const float*)d_in[8];
    const float* ne_be2= (const float*)d_in[9];
    const float* conv_w = (const float*)d_in[10];
    const float* conv_b = (const float*)d_in[11];
    const float* conv_mg= (const float*)d_in[12];
    const float* conv_mb= (const float*)d_in[13];
    const float* conv_ng= (const float*)d_in[14];
    const float* conv_nb= (const float*)d_in[15];
    const float* out_ng = (const float*)d_in[16];
    const float* out_nb = (const float*)d_in[17];
    const float* m_w1 = (const float*)d_in[18];
    const float* m_b1 = (const float*)d_in[19];
    const float* m_g1 = (const float*)d_in[20];
    const float* m_be1= (const float*)d_in[21];
    const float* m_w2 = (const float*)d_in[22];
    const float* m_b2 = (const float*)d_in[23];
    const float* m_g2 = (const float*)d_in[24];
    const float* m_be2= (const float*)d_in[25];
    const float* m_w3 = (const float*)d_in[26];
    const float* m_b3 = (const float*)d_in[27];
    const int* edge_index = (const int*)d_in[28];
    const int* batch      = (const int*)d_in[29];

    int N = in_sizes[0] / 2;
    int E = in_sizes[1] / 2;
    int B = out_size;

    int NB8 = (N + 7) / 8;
    int EB  = (E + 255) / 256;
    int nscan = (N + 511) / 512;

    zero_kernel<<<(N + 255) / 256, 256>>>(N, B);
    node_embed_kernel<<<NB8, 256>>>(x, ne_w1, ne_b1, ne_g1, ne_be1,
                                    ne_w2, ne_b2, ne_g2, ne_be2, N);
    count_deg_kernel<<<EB, 256>>>(edge_index, E);
    scan_local_kernel<<<nscan, 512>>>(N);
    scan_bsum_kernel<<<1, 256>>>(nscan);
    scan_add_kernel<<<nscan, 512>>>(N, E);
    fill_csr_kernel<<<EB, 256>>>(edge_index, edge_attr, E);

    for (int l = 0; l < 3; l++) {
        const float* cw = conv_w + l * (H + 2) * H;
        prep_layer_kernel<<<1, 32>>>(cw);
        hw_stats_kernel<<<NB8, 256>>>(cw, conv_b + l * H, N);
        conv_agg_kernel<<<NB8, 256>>>(cw,
            conv_mg + l * H, conv_mb + l * H,
            conv_ng + l * H, conv_nb + l * H,
            out_ng + l * H, out_nb + l * H,
            batch, (l == 2) ? 1 : 0, N);
    }

    head_kernel<<<(B + 7) / 8, 256>>>(m_w1, m_b1, m_g1, m_be1,
                                      m_w2, m_b2, m_g2, m_be2,
                                      m_w3, m_b3, (float*)d_out, B);
}